// round 6
// baseline (speedup 1.0000x reference)
#include <cuda_runtime.h>
#include <cstdint>

// ---------------------------------------------------------------------------
// Fused per-pixel MLP discriminator + BCE mean — INT8 IMMA version.
//   x[4,19,256,512] -> 1x1 convs 19->64->128->256->512->1 (leaky 0.2) -> BCE mean
// CTA = 128 pixels, 512 threads (16 warps = 4 M-groups x 4 N-slices).
// mma.sync m16n8k32.s8 (4096 MAC/instr = 2x fp16 path). Weights int8 with
// per-column scale + zero-sum rounding compensation; activations int8 with
// per-pixel-row dynamic scale; int32 exact accumulation; fp32 epilogues.
// Weights streamed GMEM->SMEM via cp.async (K=32 chunks, 4-slot ring, depth 3).
// Layer4+5 fused in the epilogue (h4 never materialized).
// ---------------------------------------------------------------------------

#define HW_   (256 * 512)
#define NPIX  (4 * HW_)
#define LEAK  0.2f

#define NCHUNKS    23
#define SLOT_BYTES 8192

// Packed int8 weights, chunk-major. Within a chunk (cols x 32 k), byte
//   [(ncl*4 + tq)*8 + hi*4 + j] = Wq[col][hi*16 + tq*4 + j]
// so thread tq loads uint2 = exact {b0,b1} B-fragment of m16n8k32.
__device__ __align__(16) int8_t g_Wpk[174080];
__device__ float g_sw[960];          // per-column dequant scales (L1|L2|L3|L4)
__device__ double g_acc;

__constant__ int c_gb[23] = {0, 2048, 6144, 10240, 18432, 26624, 34816,
    43008, 51200, 59392, 67584, 75776, 83968, 92160, 100352, 108544, 116736,
    124928, 133120, 141312, 149504, 157696, 165888};
__constant__ int c_sz[23] = {2048, 4096, 4096, 8192, 8192, 8192, 8192,
    8192, 8192, 8192, 8192, 8192, 8192, 8192, 8192, 8192, 8192, 8192, 8192,
    8192, 8192, 8192, 8192};

// One thread per output column: quantize with per-column scale, then flip the
// roundings with largest error so the per-column error sum ~ 0 (kills the
// systematic coupling to the mean activation).
__global__ void prep_kernel(const float* __restrict__ W1, const float* __restrict__ W2,
                            const float* __restrict__ W3, const float* __restrict__ W4) {
    const int col = blockIdx.x * blockDim.x + threadIdx.x;
    if (col == 0) g_acc = 0.0;
    if (col >= 960) return;

    const float* Wrow; int K, nc, layer;
    if (col < 64)       { layer = 0; nc = col;       K = 19;  Wrow = W1 + nc * 19;  }
    else if (col < 192) { layer = 1; nc = col - 64;  K = 64;  Wrow = W2 + nc * 64;  }
    else if (col < 448) { layer = 2; nc = col - 192; K = 128; Wrow = W3 + nc * 128; }
    else                { layer = 3; nc = col - 448; K = 256; Wrow = W4 + nc * 256; }

    float w[256]; float m = 0.f;
    for (int k = 0; k < K; ++k) { w[k] = Wrow[k]; m = fmaxf(m, fabsf(w[k])); }
    const float qsc = (m > 0.f) ? 127.f / m : 0.f;

    int q[256]; float err[256]; float R = 0.f;
    for (int k = 0; k < K; ++k) {
        const float t = w[k] * qsc;
        const float r = rintf(t);
        q[k] = (int)r; err[k] = r - t; R += err[k];
    }
    int madj = (int)rintf(R);
    while (madj != 0) {                      // zero-sum compensation
        const int s = (madj > 0) ? 1 : -1;
        int best = -1; float bv = -1e30f;
        for (int k = 0; k < K; ++k) {
            const float e = err[k] * (float)s;
            if (e > bv && s * q[k] > -127) { bv = e; best = k; }
        }
        if (best < 0) break;
        q[best] -= s; err[best] -= (float)s; madj -= s;
    }

    const int Kp = (layer == 0) ? 32 : K;    // pad L1 K 19->32 with zeros
    for (int k = 0; k < Kp; ++k) {
        const int8_t qb = (k < K) ? (int8_t)q[k] : (int8_t)0;
        int base, ncl = nc;
        if (layer == 0)      base = 0;
        else if (layer == 1) base = 2048  + (k >> 5) * 4096;
        else if (layer == 2) base = 10240 + (k >> 5) * 8192;
        else { base = 43008 + ((nc >> 8) * 8 + (k >> 5)) * 8192; ncl = nc & 255; }
        const int kl = k & 31, tq = (kl >> 2) & 3, hi = kl >> 4, j = kl & 3;
        g_Wpk[base + (ncl * 4 + tq) * 8 + hi * 4 + j] = qb;
    }
    g_sw[col] = (m > 0.f) ? m * (1.f / 127.f) : 0.f;
}

__device__ __forceinline__ float leaky(float v) { return fmaxf(v, LEAK * v); }

__device__ __forceinline__ void imma(int* c, const uint32_t* a, uint32_t b0, uint32_t b1) {
    asm volatile(
        "mma.sync.aligned.m16n8k32.row.col.s32.s8.s8.s32 "
        "{%0,%1,%2,%3},{%4,%5,%6,%7},{%8,%9},{%0,%1,%2,%3};\n"
        : "+r"(c[0]), "+r"(c[1]), "+r"(c[2]), "+r"(c[3])
        : "r"(a[0]), "r"(a[1]), "r"(a[2]), "r"(a[3]), "r"(b0), "r"(b1));
}

__device__ __forceinline__ void cp_async16(void* dst, const void* src) {
    const uint32_t d = (uint32_t)__cvta_generic_to_shared(dst);
    asm volatile("cp.async.cg.shared.global [%0], [%1], 16;\n" :: "r"(d), "l"(src) : "memory");
}
__device__ __forceinline__ void cp_commit() {
    asm volatile("cp.async.commit_group;\n" ::: "memory");
}
template <int N> __device__ __forceinline__ void cp_wait() {
    asm volatile("cp.async.wait_group %0;\n" :: "n"(N) : "memory");
}

__device__ __forceinline__ void stage_chunk(int c, char* ring, int tid) {
    if (c < NCHUNKS) {
        char* dst = ring + (c & 3) * SLOT_BYTES;
        const char* src = (const char*)g_Wpk + c_gb[c];
        const int bytes = c_sz[c];
        for (int off = tid * 16; off < bytes; off += 512 * 16)
            cp_async16(dst + off, src + off);
    }
    cp_commit();
}

// SMEM offsets (bytes). Row strides 48/80/144/272 are odd multiples of 16
// -> conflict-free ldmatrix.
#define SO_XS    0
#define SO_H1    6144
#define SO_H2    16384
#define SO_H3    34816
#define SO_RING  69632
#define SO_BIAS  102400
#define SO_W5    106240
#define SO_SW    108288
#define SO_DS0   112128
#define SO_DS1   112640
#define SO_QS    113152
#define SO_RMAX  113664
#define SO_ZS    114176
#define SO_RED   114688
#define SMEM_BYTES 114752

// One GEMM pass: A = [128 x KP] int8 in SMEM (row stride SS bytes), weights
// streamed (KP/32 chunks), NW cols/warp. Epilogue dequants (saIn row scales x
// swc col scales), bias+leaky; non-FUSE: computes new row max -> quantizes h
// to int8 (stride DS); FUSE: dots with w5 into zacc[4].
template <int KP, int NW, int SS, int DS, bool FUSE>
__device__ __forceinline__ void run_pass(
    const int8_t* sA, int8_t* sD, char* ring,
    const float* __restrict__ bias, const float* __restrict__ swc,
    const float* saIn, float* dsOut, float* sqs, unsigned* rmax,
    const float* w5, float* zacc,
    int ncol0, int chunk_col0, int& chunk, int wm, int lane, int tid)
{
    constexpr int N8 = NW / 8;
    const int g = lane >> 2, tq = lane & 3;

    int acc[2][N8][4];
#pragma unroll
    for (int t = 0; t < 2; ++t)
#pragma unroll
        for (int n = 0; n < N8; ++n)
#pragma unroll
            for (int q = 0; q < 4; ++q) acc[t][n][q] = 0;

    uint32_t abase[2];
#pragma unroll
    for (int t = 0; t < 2; ++t)
        abase[t] = (uint32_t)__cvta_generic_to_shared(
            sA + (wm * 32 + t * 16 + (lane & 15)) * SS) + ((lane >> 4) << 4);

    const int wbase = (ncol0 - chunk_col0) * 4 + tq;

#pragma unroll 1
    for (int cc = 0; cc < KP / 32; ++cc) {
        cp_wait<2>();
        __syncthreads();                       // also orders prev epilogue stores
        stage_chunk(chunk + 3, ring, tid);     // safe: all warps done with slot
        const char* slot = ring + (chunk & 3) * SLOT_BYTES;

        uint32_t a[2][4];
#pragma unroll
        for (int t = 0; t < 2; ++t)
            asm volatile("ldmatrix.sync.aligned.m8n8.x4.shared.b16 {%0,%1,%2,%3},[%4];\n"
                : "=r"(a[t][0]), "=r"(a[t][1]), "=r"(a[t][2]), "=r"(a[t][3])
                : "r"(abase[t] + cc * 32));

#pragma unroll
        for (int n8 = 0; n8 < N8; ++n8) {
            const uint2 wv = *(const uint2*)(slot + ((wbase + (n8 * 8 + g) * 4) << 3));
            imma(acc[0][n8], a[0], wv.x, wv.y);
            imma(acc[1][n8], a[1], wv.x, wv.y);
        }
        ++chunk;
    }

    // ---- epilogue ----
    const int r0 = wm * 32 + g;
    const float sa00 = saIn[r0],      sa01 = saIn[r0 + 8];
    const float sa10 = saIn[r0 + 16], sa11 = saIn[r0 + 24];
    float lm[2][2] = {{0.f, 0.f}, {0.f, 0.f}};

#pragma unroll
    for (int t = 0; t < 2; ++t) {
        const float sA0 = t ? sa10 : sa00, sA1 = t ? sa11 : sa01;
#pragma unroll
        for (int n8 = 0; n8 < N8; ++n8) {
            const int c0 = ncol0 + n8 * 8 + tq * 2;
            const float sw0 = swc[c0], sw1 = swc[c0 + 1];
            const float bb0 = bias[c0], bb1 = bias[c0 + 1];
            const float v0 = leaky(fmaf((float)acc[t][n8][0], sA0 * sw0, bb0));
            const float v1 = leaky(fmaf((float)acc[t][n8][1], sA0 * sw1, bb1));
            const float v2 = leaky(fmaf((float)acc[t][n8][2], sA1 * sw0, bb0));
            const float v3 = leaky(fmaf((float)acc[t][n8][3], sA1 * sw1, bb1));
            if (FUSE) {
                const float w50 = w5[c0], w51 = w5[c0 + 1];
                zacc[t * 2 + 0] += v0 * w50 + v1 * w51;
                zacc[t * 2 + 1] += v2 * w50 + v3 * w51;
            } else {
                lm[t][0] = fmaxf(lm[t][0], fmaxf(fabsf(v0), fabsf(v1)));
                lm[t][1] = fmaxf(lm[t][1], fmaxf(fabsf(v2), fabsf(v3)));
                acc[t][n8][0] = __float_as_int(v0); acc[t][n8][1] = __float_as_int(v1);
                acc[t][n8][2] = __float_as_int(v2); acc[t][n8][3] = __float_as_int(v3);
            }
        }
    }

    if (!FUSE) {
#pragma unroll
        for (int t = 0; t < 2; ++t) {
            atomicMax(&rmax[r0 + t * 16],     __float_as_uint(lm[t][0]));
            atomicMax(&rmax[r0 + t * 16 + 8], __float_as_uint(lm[t][1]));
        }
        __syncthreads();
        if (tid < 128) {
            const float m = __uint_as_float(rmax[tid]);
            sqs[tid]  = (m > 0.f) ? 127.f / m : 0.f;
            dsOut[tid] = m * (1.f / 127.f);
            rmax[tid] = 0u;
        }
        __syncthreads();
#pragma unroll
        for (int t = 0; t < 2; ++t) {
            const int r = r0 + t * 16;
            const float q0s = sqs[r], q1s = sqs[r + 8];
#pragma unroll
            for (int n8 = 0; n8 < N8; ++n8) {
                const int c0 = ncol0 + n8 * 8 + tq * 2;
                const int i0 = (int)rintf(__int_as_float(acc[t][n8][0]) * q0s);
                const int i1 = (int)rintf(__int_as_float(acc[t][n8][1]) * q0s);
                const int i2 = (int)rintf(__int_as_float(acc[t][n8][2]) * q1s);
                const int i3 = (int)rintf(__int_as_float(acc[t][n8][3]) * q1s);
                *(uint16_t*)(sD + r * DS + c0) =
                    (uint16_t)((i0 & 0xFF) | ((i1 & 0xFF) << 8));
                *(uint16_t*)(sD + (r + 8) * DS + c0) =
                    (uint16_t)((i2 & 0xFF) | ((i3 & 0xFF) << 8));
            }
        }
    }
}

__global__ void __launch_bounds__(512, 1)
disc_kernel(const float* __restrict__ x, const float* __restrict__ lbl,
            const float* __restrict__ b1, const float* __restrict__ b2,
            const float* __restrict__ b3, const float* __restrict__ b4,
            const float* __restrict__ W5, const float* __restrict__ b5)
{
    extern __shared__ char sm[];
    int8_t* xs = (int8_t*)(sm + SO_XS);
    int8_t* h1 = (int8_t*)(sm + SO_H1);
    int8_t* h2 = (int8_t*)(sm + SO_H2);
    int8_t* h3 = (int8_t*)(sm + SO_H3);
    char*  ring = sm + SO_RING;
    float* sbias = (float*)(sm + SO_BIAS);
    float* sw5   = (float*)(sm + SO_W5);
    float* ssw   = (float*)(sm + SO_SW);
    float* ds0   = (float*)(sm + SO_DS0);
    float* ds1   = (float*)(sm + SO_DS1);
    float* sqs   = (float*)(sm + SO_QS);
    unsigned* rmax = (unsigned*)(sm + SO_RMAX);
    float* zs  = (float*)(sm + SO_ZS);
    float* red = (float*)(sm + SO_RED);

    const int tid = threadIdx.x, wid = tid >> 5, lane = tid & 31;
    const int wm = wid >> 2, wn = wid & 3;
    const int P0 = blockIdx.x * 128;
    const int b  = P0 / HW_, s0 = P0 % HW_;

    stage_chunk(0, ring, tid);
    stage_chunk(1, ring, tid);
    stage_chunk(2, ring, tid);

    for (int i = tid; i < 960; i += 512) {
        sbias[i] = (i < 64) ? b1[i] : (i < 192) ? b2[i - 64]
                 : (i < 448) ? b3[i - 192] : b4[i - 448];
        ssw[i] = g_sw[i];
    }
    if (tid < 512) sw5[tid] = W5[tid];
    if (tid < 128) { rmax[tid] = 0u; zs[tid] = 0.f; }

    // x tile: 4 threads per pixel, quantize per-pixel over 19 channels
    {
        const int p = tid >> 2, q4 = tid & 3;
        float xv[5]; float m = 0.f;
#pragma unroll
        for (int j = 0; j < 5; ++j) {
            const int c = q4 * 5 + j;
            xv[j] = (c < 19) ? x[(b * 19 + c) * HW_ + s0 + p] : 0.f;
            m = fmaxf(m, fabsf(xv[j]));
        }
        m = fmaxf(m, __shfl_xor_sync(0xffffffffu, m, 1));
        m = fmaxf(m, __shfl_xor_sync(0xffffffffu, m, 2));
        const float qsx = (m > 0.f) ? 127.f / m : 0.f;
        if (q4 == 0) ds0[p] = m * (1.f / 127.f);
#pragma unroll
        for (int j = 0; j < 5; ++j) {
            const int c = q4 * 5 + j;
            if (c < 19) xs[p * 48 + c] = (int8_t)(int)rintf(xv[j] * qsx);
        }
        for (int i = tid; i < 128 * 13; i += 512) {   // zero-pad k 19..31
            const int pp = i / 13, cc = 19 + i % 13;
            xs[pp * 48 + cc] = 0;
        }
    }

    int chunk = 0;
    run_pass<32,  16, 48,  80,  false>(xs, h1, ring, sbias,       ssw,       ds0, ds1, sqs, rmax,
                                       nullptr, nullptr, wn * 16, 0, chunk, wm, lane, tid);
    run_pass<64,  32, 80,  144, false>(h1, h2, ring, sbias + 64,  ssw + 64,  ds1, ds0, sqs, rmax,
                                       nullptr, nullptr, wn * 32, 0, chunk, wm, lane, tid);
    run_pass<128, 64, 144, 272, false>(h2, h3, ring, sbias + 192, ssw + 192, ds0, ds1, sqs, rmax,
                                       nullptr, nullptr, wn * 64, 0, chunk, wm, lane, tid);

    float zacc[4] = {0.f, 0.f, 0.f, 0.f};
    run_pass<256, 64, 272, 1, true>(h3, nullptr, ring, sbias + 448, ssw + 448, ds1,
                                    nullptr, nullptr, nullptr, sw5, zacc,
                                    wn * 64, 0, chunk, wm, lane, tid);
    run_pass<256, 64, 272, 1, true>(h3, nullptr, ring, sbias + 448, ssw + 448, ds1,
                                    nullptr, nullptr, nullptr, sw5, zacc,
                                    256 + wn * 64, 256, chunk, wm, lane, tid);

#pragma unroll
    for (int q = 0; q < 4; ++q) {
        zacc[q] += __shfl_xor_sync(0xffffffffu, zacc[q], 1);
        zacc[q] += __shfl_xor_sync(0xffffffffu, zacc[q], 2);
    }
    if ((lane & 3) == 0) {
        const int g = lane >> 2;
#pragma unroll
        for (int q = 0; q < 4; ++q)
            atomicAdd(&zs[wm * 32 + (q >> 1) * 16 + (q & 1) * 8 + g], zacc[q]);
    }
    __syncthreads();

    if (tid < 128) {
        const float z = zs[tid] + b5[0];
        const float l = lbl[P0 + tid];
        float bce = fmaxf(z, 0.f) - z * l + log1pf(expf(-fabsf(z)));
#pragma unroll
        for (int o = 16; o > 0; o >>= 1) bce += __shfl_xor_sync(0xffffffffu, bce, o);
        if (lane == 0) red[wid] = bce;
    }
    __syncthreads();
    if (tid == 0) atomicAdd(&g_acc, (double)(red[0] + red[1] + red[2] + red[3]));
}

__global__ void fin_kernel(float* out) {
    out[0] = (float)(g_acc * (1.0 / (double)NPIX));
}

extern "C" void kernel_launch(void* const* d_in, const int* in_sizes, int n_in,
                              void* d_out, int out_size) {
    (void)in_sizes; (void)n_in; (void)out_size;
    const float* x   = (const float*)d_in[0];
    const float* lbl = (const float*)d_in[1];
    const float* W1  = (const float*)d_in[2];
    const float* b1  = (const float*)d_in[3];
    const float* W2  = (const float*)d_in[4];
    const float* b2  = (const float*)d_in[5];
    const float* W3  = (const float*)d_in[6];
    const float* b3  = (const float*)d_in[7];
    const float* W4  = (const float*)d_in[8];
    const float* b4  = (const float*)d_in[9];
    const float* W5  = (const float*)d_in[10];
    const float* b5  = (const float*)d_in[11];

    cudaFuncSetAttribute(disc_kernel, cudaFuncAttributeMaxDynamicSharedMemorySize, SMEM_BYTES);

    prep_kernel<<<4, 256>>>(W1, W2, W3, W4);
    disc_kernel<<<NPIX / 128, 512, SMEM_BYTES>>>(x, lbl, b1, b2, b3, b4, W5, b5);
    fin_kernel<<<1, 1>>>((float*)d_out);
}

// round 7
// speedup vs baseline: 1.3732x; 1.3732x over previous
#include <cuda_runtime.h>
#include <cstdint>

// ---------------------------------------------------------------------------
// Fused per-pixel MLP discriminator + BCE mean — INT8 IMMA version.
//   x[4,19,256,512] -> 1x1 convs 19->64->128->256->512->1 (leaky 0.2) -> BCE mean
// CTA = 128 pixels, 512 threads (16 warps = 4 M-groups x 4 N-slices).
// mma.sync m16n8k32.s8. Weights int8 per-column scale + error-feedback
// rounding (|per-column error sum| <= 0.5 LSB); activations int8 with
// per-pixel-row dynamic scale; int32 exact accumulation; fp32 epilogues.
// Weights streamed GMEM->SMEM via cp.async (K=32 chunks, 4-slot ring, depth 3).
// Layer4+5 fused in the epilogue (h4 never materialized).
// R7: prep rewritten as streaming error-feedback (was 345us of spilled local-
//     memory compensation loops; now O(K) with no arrays).
// ---------------------------------------------------------------------------

#define HW_   (256 * 512)
#define NPIX  (4 * HW_)
#define LEAK  0.2f

#define NCHUNKS    23
#define SLOT_BYTES 8192

// Packed int8 weights, chunk-major. Within a chunk (cols x 32 k), byte
//   [(ncl*4 + tq)*8 + hi*4 + j] = Wq[col][hi*16 + tq*4 + j]
// so thread tq loads uint2 = exact {b0,b1} B-fragment of m16n8k32.
__device__ __align__(16) int8_t g_Wpk[174080];
__device__ float g_sw[960];          // per-column dequant scales (L1|L2|L3|L4)
__device__ double g_acc;

__constant__ int c_gb[23] = {0, 2048, 6144, 10240, 18432, 26624, 34816,
    43008, 51200, 59392, 67584, 75776, 83968, 92160, 100352, 108544, 116736,
    124928, 133120, 141312, 149504, 157696, 165888};
__constant__ int c_sz[23] = {2048, 4096, 4096, 8192, 8192, 8192, 8192,
    8192, 8192, 8192, 8192, 8192, 8192, 8192, 8192, 8192, 8192, 8192, 8192,
    8192, 8192, 8192, 8192};

// One thread per output column. Pass 1: column max. Pass 2: quantize with
// error-feedback (carry e) so the column's total rounding error stays <=0.5
// LSB -- same systematic bound as exact zero-sum compensation, but streaming.
__global__ void prep_kernel(const float* __restrict__ W1, const float* __restrict__ W2,
                            const float* __restrict__ W3, const float* __restrict__ W4) {
    const int col = blockIdx.x * blockDim.x + threadIdx.x;
    if (col == 0) g_acc = 0.0;
    if (col >= 960) return;

    const float* Wrow; int K, nc, layer;
    if (col < 64)       { layer = 0; nc = col;       K = 19;  Wrow = W1 + nc * 19;  }
    else if (col < 192) { layer = 1; nc = col - 64;  K = 64;  Wrow = W2 + nc * 64;  }
    else if (col < 448) { layer = 2; nc = col - 192; K = 128; Wrow = W3 + nc * 128; }
    else                { layer = 3; nc = col - 448; K = 256; Wrow = W4 + nc * 256; }

    float m = 0.f;
    for (int k = 0; k < K; ++k) m = fmaxf(m, fabsf(Wrow[k]));
    const float qsc = (m > 0.f) ? 127.f / m : 0.f;

    const int Kp = (layer == 0) ? 32 : K;    // pad L1 K 19->32 with zeros
    float e = 0.f;
    for (int k = 0; k < Kp; ++k) {
        int8_t qb = 0;
        if (k < K) {
            const float t = Wrow[k] * qsc;
            float r = rintf(t + e);
            r = fminf(127.f, fmaxf(-127.f, r));
            e += t - r;                       // carry the rounding error
            qb = (int8_t)(int)r;
        }
        int base, ncl = nc;
        if (layer == 0)      base = 0;
        else if (layer == 1) base = 2048  + (k >> 5) * 4096;
        else if (layer == 2) base = 10240 + (k >> 5) * 8192;
        else { base = 43008 + ((nc >> 8) * 8 + (k >> 5)) * 8192; ncl = nc & 255; }
        const int kl = k & 31, tq = (kl >> 2) & 3, hi = kl >> 4, j = kl & 3;
        g_Wpk[base + (ncl * 4 + tq) * 8 + hi * 4 + j] = qb;
    }
    g_sw[col] = (m > 0.f) ? m * (1.f / 127.f) : 0.f;
}

__device__ __forceinline__ float leaky(float v) { return fmaxf(v, LEAK * v); }

__device__ __forceinline__ void imma(int* c, const uint32_t* a, uint32_t b0, uint32_t b1) {
    asm volatile(
        "mma.sync.aligned.m16n8k32.row.col.s32.s8.s8.s32 "
        "{%0,%1,%2,%3},{%4,%5,%6,%7},{%8,%9},{%0,%1,%2,%3};\n"
        : "+r"(c[0]), "+r"(c[1]), "+r"(c[2]), "+r"(c[3])
        : "r"(a[0]), "r"(a[1]), "r"(a[2]), "r"(a[3]), "r"(b0), "r"(b1));
}

__device__ __forceinline__ void cp_async16(void* dst, const void* src) {
    const uint32_t d = (uint32_t)__cvta_generic_to_shared(dst);
    asm volatile("cp.async.cg.shared.global [%0], [%1], 16;\n" :: "r"(d), "l"(src) : "memory");
}
__device__ __forceinline__ void cp_commit() {
    asm volatile("cp.async.commit_group;\n" ::: "memory");
}
template <int N> __device__ __forceinline__ void cp_wait() {
    asm volatile("cp.async.wait_group %0;\n" :: "n"(N) : "memory");
}

__device__ __forceinline__ void stage_chunk(int c, char* ring, int tid) {
    if (c < NCHUNKS) {
        char* dst = ring + (c & 3) * SLOT_BYTES;
        const char* src = (const char*)g_Wpk + c_gb[c];
        const int bytes = c_sz[c];
        for (int off = tid * 16; off < bytes; off += 512 * 16)
            cp_async16(dst + off, src + off);
    }
    cp_commit();
}

// SMEM offsets (bytes). Row strides 48/80/144/272 are odd multiples of 16
// -> conflict-free ldmatrix.
#define SO_XS    0
#define SO_H1    6144
#define SO_H2    16384
#define SO_H3    34816
#define SO_RING  69632
#define SO_BIAS  102400
#define SO_W5    106240
#define SO_SW    108288
#define SO_DS0   112128
#define SO_DS1   112640
#define SO_QS    113152
#define SO_RMAX  113664
#define SO_ZS    114176
#define SO_RED   114688
#define SMEM_BYTES 114752

// One GEMM pass: A = [128 x KP] int8 in SMEM (row stride SS bytes), weights
// streamed (KP/32 chunks), NW cols/warp. Epilogue dequants (saIn row scales x
// swc col scales), bias+leaky; non-FUSE: computes new row max -> quantizes h
// to int8 (stride DS); FUSE: dots with w5 into zacc[4].
template <int KP, int NW, int SS, int DS, bool FUSE>
__device__ __forceinline__ void run_pass(
    const int8_t* sA, int8_t* sD, char* ring,
    const float* __restrict__ bias, const float* __restrict__ swc,
    const float* saIn, float* dsOut, float* sqs, unsigned* rmax,
    const float* w5, float* zacc,
    int ncol0, int chunk_col0, int& chunk, int wm, int lane, int tid)
{
    constexpr int N8 = NW / 8;
    const int g = lane >> 2, tq = lane & 3;

    int acc[2][N8][4];
#pragma unroll
    for (int t = 0; t < 2; ++t)
#pragma unroll
        for (int n = 0; n < N8; ++n)
#pragma unroll
            for (int q = 0; q < 4; ++q) acc[t][n][q] = 0;

    uint32_t abase[2];
#pragma unroll
    for (int t = 0; t < 2; ++t)
        abase[t] = (uint32_t)__cvta_generic_to_shared(
            sA + (wm * 32 + t * 16 + (lane & 15)) * SS) + ((lane >> 4) << 4);

    const int wbase = (ncol0 - chunk_col0) * 4 + tq;

#pragma unroll 1
    for (int cc = 0; cc < KP / 32; ++cc) {
        cp_wait<2>();
        __syncthreads();                       // also orders prev epilogue stores
        stage_chunk(chunk + 3, ring, tid);     // safe: all warps done with slot
        const char* slot = ring + (chunk & 3) * SLOT_BYTES;

        uint32_t a[2][4];
#pragma unroll
        for (int t = 0; t < 2; ++t)
            asm volatile("ldmatrix.sync.aligned.m8n8.x4.shared.b16 {%0,%1,%2,%3},[%4];\n"
                : "=r"(a[t][0]), "=r"(a[t][1]), "=r"(a[t][2]), "=r"(a[t][3])
                : "r"(abase[t] + cc * 32));

#pragma unroll
        for (int n8 = 0; n8 < N8; ++n8) {
            const uint2 wv = *(const uint2*)(slot + ((wbase + (n8 * 8 + g) * 4) << 3));
            imma(acc[0][n8], a[0], wv.x, wv.y);
            imma(acc[1][n8], a[1], wv.x, wv.y);
        }
        ++chunk;
    }

    // ---- epilogue ----
    const int r0 = wm * 32 + g;
    const float sa00 = saIn[r0],      sa01 = saIn[r0 + 8];
    const float sa10 = saIn[r0 + 16], sa11 = saIn[r0 + 24];
    float lm[2][2] = {{0.f, 0.f}, {0.f, 0.f}};

#pragma unroll
    for (int t = 0; t < 2; ++t) {
        const float sA0 = t ? sa10 : sa00, sA1 = t ? sa11 : sa01;
#pragma unroll
        for (int n8 = 0; n8 < N8; ++n8) {
            const int c0 = ncol0 + n8 * 8 + tq * 2;
            const float sw0 = swc[c0], sw1 = swc[c0 + 1];
            const float bb0 = bias[c0], bb1 = bias[c0 + 1];
            const float v0 = leaky(fmaf((float)acc[t][n8][0], sA0 * sw0, bb0));
            const float v1 = leaky(fmaf((float)acc[t][n8][1], sA0 * sw1, bb1));
            const float v2 = leaky(fmaf((float)acc[t][n8][2], sA1 * sw0, bb0));
            const float v3 = leaky(fmaf((float)acc[t][n8][3], sA1 * sw1, bb1));
            if (FUSE) {
                const float w50 = w5[c0], w51 = w5[c0 + 1];
                zacc[t * 2 + 0] += v0 * w50 + v1 * w51;
                zacc[t * 2 + 1] += v2 * w50 + v3 * w51;
            } else {
                lm[t][0] = fmaxf(lm[t][0], fmaxf(fabsf(v0), fabsf(v1)));
                lm[t][1] = fmaxf(lm[t][1], fmaxf(fabsf(v2), fabsf(v3)));
                acc[t][n8][0] = __float_as_int(v0); acc[t][n8][1] = __float_as_int(v1);
                acc[t][n8][2] = __float_as_int(v2); acc[t][n8][3] = __float_as_int(v3);
            }
        }
    }

    if (!FUSE) {
#pragma unroll
        for (int t = 0; t < 2; ++t) {
            atomicMax(&rmax[r0 + t * 16],     __float_as_uint(lm[t][0]));
            atomicMax(&rmax[r0 + t * 16 + 8], __float_as_uint(lm[t][1]));
        }
        __syncthreads();
        if (tid < 128) {
            const float m = __uint_as_float(rmax[tid]);
            sqs[tid]  = (m > 0.f) ? 127.f / m : 0.f;
            dsOut[tid] = m * (1.f / 127.f);
            rmax[tid] = 0u;
        }
        __syncthreads();
#pragma unroll
        for (int t = 0; t < 2; ++t) {
            const int r = r0 + t * 16;
            const float q0s = sqs[r], q1s = sqs[r + 8];
#pragma unroll
            for (int n8 = 0; n8 < N8; ++n8) {
                const int c0 = ncol0 + n8 * 8 + tq * 2;
                const int i0 = (int)rintf(__int_as_float(acc[t][n8][0]) * q0s);
                const int i1 = (int)rintf(__int_as_float(acc[t][n8][1]) * q0s);
                const int i2 = (int)rintf(__int_as_float(acc[t][n8][2]) * q1s);
                const int i3 = (int)rintf(__int_as_float(acc[t][n8][3]) * q1s);
                *(uint16_t*)(sD + r * DS + c0) =
                    (uint16_t)((i0 & 0xFF) | ((i1 & 0xFF) << 8));
                *(uint16_t*)(sD + (r + 8) * DS + c0) =
                    (uint16_t)((i2 & 0xFF) | ((i3 & 0xFF) << 8));
            }
        }
    }
}

__global__ void __launch_bounds__(512, 1)
disc_kernel(const float* __restrict__ x, const float* __restrict__ lbl,
            const float* __restrict__ b1, const float* __restrict__ b2,
            const float* __restrict__ b3, const float* __restrict__ b4,
            const float* __restrict__ W5, const float* __restrict__ b5)
{
    extern __shared__ char sm[];
    int8_t* xs = (int8_t*)(sm + SO_XS);
    int8_t* h1 = (int8_t*)(sm + SO_H1);
    int8_t* h2 = (int8_t*)(sm + SO_H2);
    int8_t* h3 = (int8_t*)(sm + SO_H3);
    char*  ring = sm + SO_RING;
    float* sbias = (float*)(sm + SO_BIAS);
    float* sw5   = (float*)(sm + SO_W5);
    float* ssw   = (float*)(sm + SO_SW);
    float* ds0   = (float*)(sm + SO_DS0);
    float* ds1   = (float*)(sm + SO_DS1);
    float* sqs   = (float*)(sm + SO_QS);
    unsigned* rmax = (unsigned*)(sm + SO_RMAX);
    float* zs  = (float*)(sm + SO_ZS);
    float* red = (float*)(sm + SO_RED);

    const int tid = threadIdx.x, wid = tid >> 5, lane = tid & 31;
    const int wm = wid >> 2, wn = wid & 3;
    const int P0 = blockIdx.x * 128;
    const int b  = P0 / HW_, s0 = P0 % HW_;

    stage_chunk(0, ring, tid);
    stage_chunk(1, ring, tid);
    stage_chunk(2, ring, tid);

    for (int i = tid; i < 960; i += 512) {
        sbias[i] = (i < 64) ? b1[i] : (i < 192) ? b2[i - 64]
                 : (i < 448) ? b3[i - 192] : b4[i - 448];
        ssw[i] = g_sw[i];
    }
    if (tid < 512) sw5[tid] = W5[tid];
    if (tid < 128) { rmax[tid] = 0u; zs[tid] = 0.f; }

    // x tile: 4 threads per pixel, quantize per-pixel over 19 channels
    {
        const int p = tid >> 2, q4 = tid & 3;
        float xv[5]; float m = 0.f;
#pragma unroll
        for (int j = 0; j < 5; ++j) {
            const int c = q4 * 5 + j;
            xv[j] = (c < 19) ? x[(b * 19 + c) * HW_ + s0 + p] : 0.f;
            m = fmaxf(m, fabsf(xv[j]));
        }
        m = fmaxf(m, __shfl_xor_sync(0xffffffffu, m, 1));
        m = fmaxf(m, __shfl_xor_sync(0xffffffffu, m, 2));
        const float qsx = (m > 0.f) ? 127.f / m : 0.f;
        if (q4 == 0) ds0[p] = m * (1.f / 127.f);
#pragma unroll
        for (int j = 0; j < 5; ++j) {
            const int c = q4 * 5 + j;
            if (c < 19) xs[p * 48 + c] = (int8_t)(int)rintf(xv[j] * qsx);
        }
        for (int i = tid; i < 128 * 13; i += 512) {   // zero-pad k 19..31
            const int pp = i / 13, cc = 19 + i % 13;
            xs[pp * 48 + cc] = 0;
        }
    }

    int chunk = 0;
    run_pass<32,  16, 48,  80,  false>(xs, h1, ring, sbias,       ssw,       ds0, ds1, sqs, rmax,
                                       nullptr, nullptr, wn * 16, 0, chunk, wm, lane, tid);
    run_pass<64,  32, 80,  144, false>(h1, h2, ring, sbias + 64,  ssw + 64,  ds1, ds0, sqs, rmax,
                                       nullptr, nullptr, wn * 32, 0, chunk, wm, lane, tid);
    run_pass<128, 64, 144, 272, false>(h2, h3, ring, sbias + 192, ssw + 192, ds0, ds1, sqs, rmax,
                                       nullptr, nullptr, wn * 64, 0, chunk, wm, lane, tid);

    float zacc[4] = {0.f, 0.f, 0.f, 0.f};
    run_pass<256, 64, 272, 1, true>(h3, nullptr, ring, sbias + 448, ssw + 448, ds1,
                                    nullptr, nullptr, nullptr, sw5, zacc,
                                    wn * 64, 0, chunk, wm, lane, tid);
    run_pass<256, 64, 272, 1, true>(h3, nullptr, ring, sbias + 448, ssw + 448, ds1,
                                    nullptr, nullptr, nullptr, sw5, zacc,
                                    256 + wn * 64, 256, chunk, wm, lane, tid);

#pragma unroll
    for (int q = 0; q < 4; ++q) {
        zacc[q] += __shfl_xor_sync(0xffffffffu, zacc[q], 1);
        zacc[q] += __shfl_xor_sync(0xffffffffu, zacc[q], 2);
    }
    if ((lane & 3) == 0) {
        const int g = lane >> 2;
#pragma unroll
        for (int q = 0; q < 4; ++q)
            atomicAdd(&zs[wm * 32 + (q >> 1) * 16 + (q & 1) * 8 + g], zacc[q]);
    }
    __syncthreads();

    if (tid < 128) {
        const float z = zs[tid] + b5[0];
        const float l = lbl[P0 + tid];
        float bce = fmaxf(z, 0.f) - z * l + log1pf(expf(-fabsf(z)));
#pragma unroll
        for (int o = 16; o > 0; o >>= 1) bce += __shfl_xor_sync(0xffffffffu, bce, o);
        if (lane == 0) red[wid] = bce;
    }
    __syncthreads();
    if (tid == 0) atomicAdd(&g_acc, (double)(red[0] + red[1] + red[2] + red[3]));
}

__global__ void fin_kernel(float* out) {
    out[0] = (float)(g_acc * (1.0 / (double)NPIX));
}

extern "C" void kernel_launch(void* const* d_in, const int* in_sizes, int n_in,
                              void* d_out, int out_size) {
    (void)in_sizes; (void)n_in; (void)out_size;
    const float* x   = (const float*)d_in[0];
    const float* lbl = (const float*)d_in[1];
    const float* W1  = (const float*)d_in[2];
    const float* b1  = (const float*)d_in[3];
    const float* W2  = (const float*)d_in[4];
    const float* b2  = (const float*)d_in[5];
    const float* W3  = (const float*)d_in[6];
    const float* b3  = (const float*)d_in[7];
    const float* W4  = (const float*)d_in[8];
    const float* b4  = (const float*)d_in[9];
    const float* W5  = (const float*)d_in[10];
    const float* b5  = (const float*)d_in[11];

    cudaFuncSetAttribute(disc_kernel, cudaFuncAttributeMaxDynamicSharedMemorySize, SMEM_BYTES);

    prep_kernel<<<4, 256>>>(W1, W2, W3, W4);
    disc_kernel<<<NPIX / 128, 512, SMEM_BYTES>>>(x, lbl, b1, b2, b3, b4, W5, b5);
    fin_kernel<<<1, 1>>>((float*)d_out);
}

// round 9
// speedup vs baseline: 1.5368x; 1.1191x over previous
#include <cuda_runtime.h>
#include <cstdint>

// ---------------------------------------------------------------------------
// Fused per-pixel MLP discriminator + BCE mean — INT8 IMMA version, R8/R9.
//   x[4,19,256,512] -> 1x1 convs 19->64->128->256->512->1 (leaky 0.2) -> BCE mean
// R8: CTA = 64 pixels (M=64), 512 threads = 4 M-tiles x 4 N-slices, ~79KB smem
//     -> 2 CTAs/SM so barriers/epilogues of one CTA hide under the other's
//     IMMAs. prep rewritten with SMEM staging (coalesced loads).
// mma.sync m16n8k32.s8; weights int8 per-col scale + error-feedback rounding;
// activations int8 per-pixel dynamic scale; int32 accum; fp32 epilogues.
// Weights streamed GMEM->SMEM via cp.async (K=32 chunks, 4-slot ring, depth 3).
// Layer4+5 fused in the epilogue (h4 never materialized).
// ---------------------------------------------------------------------------

#define HW_   (256 * 512)
#define NPIX  (4 * HW_)
#define LEAK  0.2f

#define NCHUNKS    23
#define SLOT_BYTES 8192

// Packed int8 weights, chunk-major (identical layout to R7 — validated).
__device__ __align__(16) int8_t g_Wpk[174080];
__device__ float g_sw[960];
__device__ double g_acc;

__constant__ int c_gb[23] = {0, 2048, 6144, 10240, 18432, 26624, 34816,
    43008, 51200, 59392, 67584, 75776, 83968, 92160, 100352, 108544, 116736,
    124928, 133120, 141312, 149504, 157696, 165888};
__constant__ int c_sz[23] = {2048, 4096, 4096, 8192, 8192, 8192, 8192,
    8192, 8192, 8192, 8192, 8192, 8192, 8192, 8192, 8192, 8192, 8192, 8192,
    8192, 8192, 8192, 8192};

// 30 blocks x 32 columns. Cooperative coalesced load of the 32xK slab into
// SMEM, then 32 threads run the serial error-feedback quantization from SMEM.
__global__ void prep_kernel(const float* __restrict__ W1, const float* __restrict__ W2,
                            const float* __restrict__ W3, const float* __restrict__ W4) {
    __shared__ float swt[32 * 256];
    const int tid = threadIdx.x;
    const int c0 = blockIdx.x * 32;
    if (blockIdx.x == 0 && tid == 0) g_acc = 0.0;

    int layer, K, lstart;
    const float* Wl;
    if (c0 < 64)       { layer = 0; K = 19;  lstart = 0;   Wl = W1; }
    else if (c0 < 192) { layer = 1; K = 64;  lstart = 64;  Wl = W2; }
    else if (c0 < 448) { layer = 2; K = 128; lstart = 192; Wl = W3; }
    else               { layer = 3; K = 256; lstart = 448; Wl = W4; }
    const float* src = Wl + (c0 - lstart) * K;

    for (int i = tid; i < 32 * K; i += 256) swt[i] = src[i];
    __syncthreads();

    if (tid < 32) {
        const int nc = c0 - lstart + tid;
        const float* Wrow = swt + tid * K;
        float m = 0.f;
        for (int k = 0; k < K; ++k) m = fmaxf(m, fabsf(Wrow[k]));
        const float qsc = (m > 0.f) ? 127.f / m : 0.f;

        const int Kp = (layer == 0) ? 32 : K;
        float e = 0.f;
        for (int k = 0; k < Kp; ++k) {
            int8_t qb = 0;
            if (k < K) {
                const float t = Wrow[k] * qsc;
                float r = rintf(t + e);
                r = fminf(127.f, fmaxf(-127.f, r));
                e += t - r;
                qb = (int8_t)(int)r;
            }
            int base, ncl = nc;
            if (layer == 0)      base = 0;
            else if (layer == 1) base = 2048  + (k >> 5) * 4096;
            else if (layer == 2) base = 10240 + (k >> 5) * 8192;
            else { base = 43008 + ((nc >> 8) * 8 + (k >> 5)) * 8192; ncl = nc & 255; }
            const int kl = k & 31, tq = (kl >> 2) & 3, hi = kl >> 4, j = kl & 3;
            g_Wpk[base + (ncl * 4 + tq) * 8 + hi * 4 + j] = qb;
        }
        g_sw[c0 + tid] = (m > 0.f) ? m * (1.f / 127.f) : 0.f;
    }
}

__device__ __forceinline__ float leaky(float v) { return fmaxf(v, LEAK * v); }

__device__ __forceinline__ void imma(int* c, const uint32_t* a, uint32_t b0, uint32_t b1) {
    asm volatile(
        "mma.sync.aligned.m16n8k32.row.col.s32.s8.s8.s32 "
        "{%0,%1,%2,%3},{%4,%5,%6,%7},{%8,%9},{%0,%1,%2,%3};\n"
        : "+r"(c[0]), "+r"(c[1]), "+r"(c[2]), "+r"(c[3])
        : "r"(a[0]), "r"(a[1]), "r"(a[2]), "r"(a[3]), "r"(b0), "r"(b1));
}

__device__ __forceinline__ void cp_async16(void* dst, const void* src) {
    const uint32_t d = (uint32_t)__cvta_generic_to_shared(dst);
    asm volatile("cp.async.cg.shared.global [%0], [%1], 16;\n" :: "r"(d), "l"(src) : "memory");
}
__device__ __forceinline__ void cp_commit() {
    asm volatile("cp.async.commit_group;\n" ::: "memory");
}
template <int N> __device__ __forceinline__ void cp_wait() {
    asm volatile("cp.async.wait_group %0;\n" :: "n"(N) : "memory");
}

__device__ __forceinline__ void stage_chunk(int c, char* ring, int tid) {
    if (c < NCHUNKS) {
        char* dst = ring + (c & 3) * SLOT_BYTES;
        const char* src = (const char*)g_Wpk + c_gb[c];
        const int bytes = c_sz[c];
        for (int off = tid * 16; off < bytes; off += 512 * 16)
            cp_async16(dst + off, src + off);
    }
    cp_commit();
}

// SMEM offsets (bytes), M=64. Strides 48/80/144/272: 16B-aligned, conflict-free.
#define SO_XS    0          // 64*48   = 3072
#define SO_H1    3072       // 64*80   = 5120
#define SO_H2    8192       // 64*144  = 9216
#define SO_H3    17408      // 64*272  = 17408
#define SO_RING  34816      // 4*8192  = 32768
#define SO_BIAS  67584      // 960*4
#define SO_W5    71424      // 512*4
#define SO_SW    73472      // 960*4
#define SO_DS0   77312      // 64*4
#define SO_DS1   77568
#define SO_QS    77824
#define SO_RMAX  78080
#define SO_ZS    78336
#define SO_RED   78592
#define SMEM_BYTES 78656

// One GEMM pass, M=64: warp wm owns m16 tile rows [wm*16,+16), wn owns NW cols.
template <int KP, int NW, int SS, int DS, bool FUSE>
__device__ __forceinline__ void run_pass(
    const int8_t* sA, int8_t* sD, char* ring,
    const float* __restrict__ bias, const float* __restrict__ swc,
    const float* saIn, float* dsOut, float* sqs, unsigned* rmax,
    const float* w5, float* zacc,
    int ncol0, int chunk_col0, int& chunk, int wm, int lane, int tid)
{
    constexpr int N8 = NW / 8;
    const int g = lane >> 2, tq = lane & 3;

    int acc[N8][4];
#pragma unroll
    for (int n = 0; n < N8; ++n)
#pragma unroll
        for (int q = 0; q < 4; ++q) acc[n][q] = 0;

    const uint32_t abase = (uint32_t)__cvta_generic_to_shared(
        sA + (wm * 16 + (lane & 15)) * SS) + ((lane >> 4) << 4);
    const int wbase = (ncol0 - chunk_col0) * 4 + tq;

#pragma unroll 1
    for (int cc = 0; cc < KP / 32; ++cc) {
        cp_wait<2>();
        __syncthreads();
        stage_chunk(chunk + 3, ring, tid);
        const char* slot = ring + (chunk & 3) * SLOT_BYTES;

        uint32_t a[4];
        asm volatile("ldmatrix.sync.aligned.m8n8.x4.shared.b16 {%0,%1,%2,%3},[%4];\n"
            : "=r"(a[0]), "=r"(a[1]), "=r"(a[2]), "=r"(a[3])
            : "r"(abase + cc * 32));

#pragma unroll
        for (int n8 = 0; n8 < N8; ++n8) {
            const uint2 wv = *(const uint2*)(slot + ((wbase + (n8 * 8 + g) * 4) << 3));
            imma(acc[n8], a, wv.x, wv.y);
        }
        ++chunk;
    }

    // ---- epilogue: rows r0 (acc[0..1]) and r0+8 (acc[2..3]) ----
    const int r0 = wm * 16 + g;
    const float sa0 = saIn[r0], sa1 = saIn[r0 + 8];
    float lm0 = 0.f, lm1 = 0.f;

#pragma unroll
    for (int n8 = 0; n8 < N8; ++n8) {
        const int c0 = ncol0 + n8 * 8 + tq * 2;
        const float sw0 = swc[c0], sw1 = swc[c0 + 1];
        const float bb0 = bias[c0], bb1 = bias[c0 + 1];
        const float v0 = leaky(fmaf((float)acc[n8][0], sa0 * sw0, bb0));
        const float v1 = leaky(fmaf((float)acc[n8][1], sa0 * sw1, bb1));
        const float v2 = leaky(fmaf((float)acc[n8][2], sa1 * sw0, bb0));
        const float v3 = leaky(fmaf((float)acc[n8][3], sa1 * sw1, bb1));
        if (FUSE) {
            const float w50 = w5[c0], w51 = w5[c0 + 1];
            zacc[0] += v0 * w50 + v1 * w51;
            zacc[1] += v2 * w50 + v3 * w51;
        } else {
            lm0 = fmaxf(lm0, fmaxf(fabsf(v0), fabsf(v1)));
            lm1 = fmaxf(lm1, fmaxf(fabsf(v2), fabsf(v3)));
            acc[n8][0] = __float_as_int(v0); acc[n8][1] = __float_as_int(v1);
            acc[n8][2] = __float_as_int(v2); acc[n8][3] = __float_as_int(v3);
        }
    }

    if (!FUSE) {
        atomicMax(&rmax[r0],     __float_as_uint(lm0));
        atomicMax(&rmax[r0 + 8], __float_as_uint(lm1));
        __syncthreads();
        if (tid < 64) {
            const float m = __uint_as_float(rmax[tid]);
            sqs[tid]   = (m > 0.f) ? 127.f / m : 0.f;
            dsOut[tid] = m * (1.f / 127.f);
            rmax[tid]  = 0u;
        }
        __syncthreads();
        const float q0s = sqs[r0], q1s = sqs[r0 + 8];
#pragma unroll
        for (int n8 = 0; n8 < N8; ++n8) {
            const int c0 = ncol0 + n8 * 8 + tq * 2;
            const int i0 = (int)rintf(__int_as_float(acc[n8][0]) * q0s);
            const int i1 = (int)rintf(__int_as_float(acc[n8][1]) * q0s);
            const int i2 = (int)rintf(__int_as_float(acc[n8][2]) * q1s);
            const int i3 = (int)rintf(__int_as_float(acc[n8][3]) * q1s);
            *(uint16_t*)(sD + r0 * DS + c0) =
                (uint16_t)((i0 & 0xFF) | ((i1 & 0xFF) << 8));
            *(uint16_t*)(sD + (r0 + 8) * DS + c0) =
                (uint16_t)((i2 & 0xFF) | ((i3 & 0xFF) << 8));
        }
    }
}

__global__ void __launch_bounds__(512, 2)
disc_kernel(const float* __restrict__ x, const float* __restrict__ lbl,
            const float* __restrict__ b1, const float* __restrict__ b2,
            const float* __restrict__ b3, const float* __restrict__ b4,
            const float* __restrict__ W5, const float* __restrict__ b5)
{
    extern __shared__ char sm[];
    int8_t* xs = (int8_t*)(sm + SO_XS);
    int8_t* h1 = (int8_t*)(sm + SO_H1);
    int8_t* h2 = (int8_t*)(sm + SO_H2);
    int8_t* h3 = (int8_t*)(sm + SO_H3);
    char*  ring = sm + SO_RING;
    float* sbias = (float*)(sm + SO_BIAS);
    float* sw5   = (float*)(sm + SO_W5);
    float* ssw   = (float*)(sm + SO_SW);
    float* ds0   = (float*)(sm + SO_DS0);
    float* ds1   = (float*)(sm + SO_DS1);
    float* sqs   = (float*)(sm + SO_QS);
    unsigned* rmax = (unsigned*)(sm + SO_RMAX);
    float* zs  = (float*)(sm + SO_ZS);
    float* red = (float*)(sm + SO_RED);

    const int tid = threadIdx.x, wid = tid >> 5, lane = tid & 31;
    const int wm = wid >> 2, wn = wid & 3;
    const int P0 = blockIdx.x * 64;
    const int b  = P0 / HW_, s0 = P0 % HW_;

    stage_chunk(0, ring, tid);
    stage_chunk(1, ring, tid);
    stage_chunk(2, ring, tid);

    for (int i = tid; i < 960; i += 512) {
        sbias[i] = (i < 64) ? b1[i] : (i < 192) ? b2[i - 64]
                 : (i < 448) ? b3[i - 192] : b4[i - 448];
        ssw[i] = g_sw[i];
    }
    if (tid < 512) sw5[tid] = W5[tid];
    if (tid < 64) { rmax[tid] = 0u; zs[tid] = 0.f; }

    // x tile: 8 threads per pixel (3 channels each), per-pixel dynamic scale
    {
        const int p = tid >> 3, q8 = tid & 7;
        float xv[3]; float m = 0.f;
#pragma unroll
        for (int j = 0; j < 3; ++j) {
            const int c = q8 * 3 + j;
            xv[j] = (c < 19) ? x[(b * 19 + c) * HW_ + s0 + p] : 0.f;
            m = fmaxf(m, fabsf(xv[j]));
        }
        m = fmaxf(m, __shfl_xor_sync(0xffffffffu, m, 1));
        m = fmaxf(m, __shfl_xor_sync(0xffffffffu, m, 2));
        m = fmaxf(m, __shfl_xor_sync(0xffffffffu, m, 4));
        const float qsx = (m > 0.f) ? 127.f / m : 0.f;
        if (q8 == 0) ds0[p] = m * (1.f / 127.f);
#pragma unroll
        for (int j = 0; j < 3; ++j) {
            const int c = q8 * 3 + j;
            if (c < 19) xs[p * 48 + c] = (int8_t)(int)rintf(xv[j] * qsx);
        }
        for (int i = tid; i < 64 * 13; i += 512) {    // zero-pad k 19..31
            const int pp = i / 13, cc = 19 + i % 13;
            xs[pp * 48 + cc] = 0;
        }
    }

    int chunk = 0;
    run_pass<32,  16, 48,  80,  false>(xs, h1, ring, sbias,       ssw,       ds0, ds1, sqs, rmax,
                                       nullptr, nullptr, wn * 16, 0, chunk, wm, lane, tid);
    run_pass<64,  32, 80,  144, false>(h1, h2, ring, sbias + 64,  ssw + 64,  ds1, ds0, sqs, rmax,
                                       nullptr, nullptr, wn * 32, 0, chunk, wm, lane, tid);
    run_pass<128, 64, 144, 272, false>(h2, h3, ring, sbias + 192, ssw + 192, ds0, ds1, sqs, rmax,
                                       nullptr, nullptr, wn * 64, 0, chunk, wm, lane, tid);

    float zacc[2] = {0.f, 0.f};
    run_pass<256, 64, 272, 1, true>(h3, nullptr, ring, sbias + 448, ssw + 448, ds1,
                                    nullptr, nullptr, nullptr, sw5, zacc,
                                    wn * 64, 0, chunk, wm, lane, tid);
    run_pass<256, 64, 272, 1, true>(h3, nullptr, ring, sbias + 448, ssw + 448, ds1,
                                    nullptr, nullptr, nullptr, sw5, zacc,
                                    256 + wn * 64, 256, chunk, wm, lane, tid);

    zacc[0] += __shfl_xor_sync(0xffffffffu, zacc[0], 1);
    zacc[0] += __shfl_xor_sync(0xffffffffu, zacc[0], 2);
    zacc[1] += __shfl_xor_sync(0xffffffffu, zacc[1], 1);
    zacc[1] += __shfl_xor_sync(0xffffffffu, zacc[1], 2);
    if ((lane & 3) == 0) {
        const int r0 = wm * 16 + (lane >> 2);
        atomicAdd(&zs[r0],     zacc[0]);
        atomicAdd(&zs[r0 + 8], zacc[1]);
    }
    __syncthreads();

    if (tid < 64) {
        const float z = zs[tid] + b5[0];
        const float l = lbl[P0 + tid];
        float bce = fmaxf(z, 0.f) - z * l + log1pf(expf(-fabsf(z)));
#pragma unroll
        for (int o = 16; o > 0; o >>= 1) bce += __shfl_xor_sync(0xffffffffu, bce, o);
        if (lane == 0) red[wid] = bce;
    }
    __syncthreads();
    if (tid == 0) atomicAdd(&g_acc, (double)(red[0] + red[1]));
}

__global__ void fin_kernel(float* out) {
    out[0] = (float)(g_acc * (1.0 / (double)NPIX));
}

extern "C" void kernel_launch(void* const* d_in, const int* in_sizes, int n_in,
                              void* d_out, int out_size) {
    (void)in_sizes; (void)n_in; (void)out_size;
    const float* x   = (const float*)d_in[0];
    const float* lbl = (const float*)d_in[1];
    const float* W1  = (const float*)d_in[2];
    const float* b1  = (const float*)d_in[3];
    const float* W2  = (const float*)d_in[4];
    const float* b2  = (const float*)d_in[5];
    const float* W3  = (const float*)d_in[6];
    const float* b3  = (const float*)d_in[7];
    const float* W4  = (const float*)d_in[8];
    const float* b4  = (const float*)d_in[9];
    const float* W5  = (const float*)d_in[10];
    const float* b5  = (const float*)d_in[11];

    cudaFuncSetAttribute(disc_kernel, cudaFuncAttributeMaxDynamicSharedMemorySize, SMEM_BYTES);

    prep_kernel<<<30, 256>>>(W1, W2, W3, W4);
    disc_kernel<<<NPIX / 64, 512, SMEM_BYTES>>>(x, lbl, b1, b2, b3, b4, W5, b5);
    fin_kernel<<<1, 1>>>((float*)d_out);
}

// round 10
// speedup vs baseline: 1.6626x; 1.0819x over previous
#include <cuda_runtime.h>
#include <cstdint>

// ---------------------------------------------------------------------------
// Fused per-pixel MLP discriminator + BCE mean — INT8 IMMA version, R10.
//   x[4,19,256,512] -> 1x1 convs 19->64->128->256->512->1 (leaky 0.2) -> BCE mean
// disc (unchanged from R9, 2 CTAs/SM): CTA = 64 pixels, 512 threads,
//   mma.sync m16n8k32.s8, weights streamed via cp.async 4-slot ring,
//   per-pixel dynamic activation scales, L4+5 fused epilogue.
// R10: prep parallelized — error-feedback rounding computed in closed form
//   q_k = rint(cumsum_k) - rint(cumsum_{k-1}) (one warp per column, warp scan)
//   instead of the 256-step serial carry chain (was 49us at occ 2%).
// ---------------------------------------------------------------------------

#define HW_   (256 * 512)
#define NPIX  (4 * HW_)
#define LEAK  0.2f

#define NCHUNKS    23
#define SLOT_BYTES 8192

// Packed int8 weights, chunk-major (layout validated R7-R9).
__device__ __align__(16) int8_t g_Wpk[174080];
__device__ float g_sw[960];
__device__ double g_acc;

__constant__ int c_gb[23] = {0, 2048, 6144, 10240, 18432, 26624, 34816,
    43008, 51200, 59392, 67584, 75776, 83968, 92160, 100352, 108544, 116736,
    124928, 133120, 141312, 149504, 157696, 165888};
__constant__ int c_sz[23] = {2048, 4096, 4096, 8192, 8192, 8192, 8192,
    8192, 8192, 8192, 8192, 8192, 8192, 8192, 8192, 8192, 8192, 8192, 8192,
    8192, 8192, 8192, 8192};

// One WARP per output column (8 warps/block, 120 blocks).
// q_k = rint(T_k) - rint(T_{k-1}) where T = cumsum of scaled weights:
// closed form of error-feedback rounding -> |column error sum| <= 0.5 LSB.
__global__ void prep_kernel(const float* __restrict__ W1, const float* __restrict__ W2,
                            const float* __restrict__ W3, const float* __restrict__ W4) {
    const int lane = threadIdx.x & 31;
    const int col = blockIdx.x * 8 + (threadIdx.x >> 5);
    if (col == 0 && lane == 0) g_acc = 0.0;
    if (col >= 960) return;

    const float* Wrow; int K, nc, layer;
    if (col < 64)       { layer = 0; nc = col;       K = 19;  Wrow = W1 + nc * 19;  }
    else if (col < 192) { layer = 1; nc = col - 64;  K = 64;  Wrow = W2 + nc * 64;  }
    else if (col < 448) { layer = 2; nc = col - 192; K = 128; Wrow = W3 + nc * 128; }
    else                { layer = 3; nc = col - 448; K = 256; Wrow = W4 + nc * 256; }

    // Lane owns 8 contiguous k: [lane*8, lane*8+8)
    float v[8]; float m = 0.f;
#pragma unroll
    for (int j = 0; j < 8; ++j) {
        const int k = lane * 8 + j;
        v[j] = (k < K) ? Wrow[k] : 0.f;
        m = fmaxf(m, fabsf(v[j]));
    }
#pragma unroll
    for (int o = 16; o > 0; o >>= 1) m = fmaxf(m, __shfl_xor_sync(0xffffffffu, m, o));
    const float qsc = (m > 0.f) ? 127.f / m : 0.f;

    // Local inclusive prefix of scaled values.
    float p[8]; float s = 0.f;
#pragma unroll
    for (int j = 0; j < 8; ++j) { s += v[j] * qsc; p[j] = s; }

    // Warp-exclusive scan of lane totals.
    float inc = s;
#pragma unroll
    for (int o = 1; o < 32; o <<= 1) {
        const float t = __shfl_up_sync(0xffffffffu, inc, o);
        if (lane >= o) inc += t;
    }
    const float base = inc - s;              // exclusive prefix

    // q_k = rint(base+p[j]) - rint(prev); chain R unclamped, clamp stored byte.
    float Rprev = rintf(base);
    const int Kp = (layer == 0) ? 32 : K;
#pragma unroll
    for (int j = 0; j < 8; ++j) {
        const int k = lane * 8 + j;
        if (k >= Kp) break;
        const float R = rintf(base + p[j]);
        float q = R - Rprev;
        Rprev = R;
        q = fminf(127.f, fmaxf(-127.f, q));
        const int8_t qb = (k < K) ? (int8_t)(int)q : (int8_t)0;

        int bse, ncl = nc;
        if (layer == 0)      bse = 0;
        else if (layer == 1) bse = 2048  + (k >> 5) * 4096;
        else if (layer == 2) bse = 10240 + (k >> 5) * 8192;
        else { bse = 43008 + ((nc >> 8) * 8 + (k >> 5)) * 8192; ncl = nc & 255; }
        const int kl = k & 31, tq = (kl >> 2) & 3, hi = kl >> 4, jj = kl & 3;
        g_Wpk[bse + (ncl * 4 + tq) * 8 + hi * 4 + jj] = qb;
    }
    if (lane == 0) g_sw[col] = (m > 0.f) ? m * (1.f / 127.f) : 0.f;
}

__device__ __forceinline__ float leaky(float v) { return fmaxf(v, LEAK * v); }

__device__ __forceinline__ void imma(int* c, const uint32_t* a, uint32_t b0, uint32_t b1) {
    asm volatile(
        "mma.sync.aligned.m16n8k32.row.col.s32.s8.s8.s32 "
        "{%0,%1,%2,%3},{%4,%5,%6,%7},{%8,%9},{%0,%1,%2,%3};\n"
        : "+r"(c[0]), "+r"(c[1]), "+r"(c[2]), "+r"(c[3])
        : "r"(a[0]), "r"(a[1]), "r"(a[2]), "r"(a[3]), "r"(b0), "r"(b1));
}

__device__ __forceinline__ void cp_async16(void* dst, const void* src) {
    const uint32_t d = (uint32_t)__cvta_generic_to_shared(dst);
    asm volatile("cp.async.cg.shared.global [%0], [%1], 16;\n" :: "r"(d), "l"(src) : "memory");
}
__device__ __forceinline__ void cp_commit() {
    asm volatile("cp.async.commit_group;\n" ::: "memory");
}
template <int N> __device__ __forceinline__ void cp_wait() {
    asm volatile("cp.async.wait_group %0;\n" :: "n"(N) : "memory");
}

__device__ __forceinline__ void stage_chunk(int c, char* ring, int tid) {
    if (c < NCHUNKS) {
        char* dst = ring + (c & 3) * SLOT_BYTES;
        const char* src = (const char*)g_Wpk + c_gb[c];
        const int bytes = c_sz[c];
        for (int off = tid * 16; off < bytes; off += 512 * 16)
            cp_async16(dst + off, src + off);
    }
    cp_commit();
}

// SMEM offsets (bytes), M=64. Strides 48/80/144/272: 16B-aligned, conflict-free.
#define SO_XS    0
#define SO_H1    3072
#define SO_H2    8192
#define SO_H3    17408
#define SO_RING  34816
#define SO_BIAS  67584
#define SO_W5    71424
#define SO_SW    73472
#define SO_DS0   77312
#define SO_DS1   77568
#define SO_QS    77824
#define SO_RMAX  78080
#define SO_ZS    78336
#define SO_RED   78592
#define SMEM_BYTES 78656

// One GEMM pass, M=64: warp wm owns m16 tile rows [wm*16,+16), wn owns NW cols.
template <int KP, int NW, int SS, int DS, bool FUSE>
__device__ __forceinline__ void run_pass(
    const int8_t* sA, int8_t* sD, char* ring,
    const float* __restrict__ bias, const float* __restrict__ swc,
    const float* saIn, float* dsOut, float* sqs, unsigned* rmax,
    const float* w5, float* zacc,
    int ncol0, int chunk_col0, int& chunk, int wm, int lane, int tid)
{
    constexpr int N8 = NW / 8;
    const int g = lane >> 2, tq = lane & 3;

    int acc[N8][4];
#pragma unroll
    for (int n = 0; n < N8; ++n)
#pragma unroll
        for (int q = 0; q < 4; ++q) acc[n][q] = 0;

    const uint32_t abase = (uint32_t)__cvta_generic_to_shared(
        sA + (wm * 16 + (lane & 15)) * SS) + ((lane >> 4) << 4);
    const int wbase = (ncol0 - chunk_col0) * 4 + tq;

#pragma unroll 1
    for (int cc = 0; cc < KP / 32; ++cc) {
        cp_wait<2>();
        __syncthreads();
        stage_chunk(chunk + 3, ring, tid);
        const char* slot = ring + (chunk & 3) * SLOT_BYTES;

        uint32_t a[4];
        asm volatile("ldmatrix.sync.aligned.m8n8.x4.shared.b16 {%0,%1,%2,%3},[%4];\n"
            : "=r"(a[0]), "=r"(a[1]), "=r"(a[2]), "=r"(a[3])
            : "r"(abase + cc * 32));

#pragma unroll
        for (int n8 = 0; n8 < N8; ++n8) {
            const uint2 wv = *(const uint2*)(slot + ((wbase + (n8 * 8 + g) * 4) << 3));
            imma(acc[n8], a, wv.x, wv.y);
        }
        ++chunk;
    }

    // ---- epilogue: rows r0 (acc[0..1]) and r0+8 (acc[2..3]) ----
    const int r0 = wm * 16 + g;
    const float sa0 = saIn[r0], sa1 = saIn[r0 + 8];
    float lm0 = 0.f, lm1 = 0.f;

#pragma unroll
    for (int n8 = 0; n8 < N8; ++n8) {
        const int c0 = ncol0 + n8 * 8 + tq * 2;
        const float sw0 = swc[c0], sw1 = swc[c0 + 1];
        const float bb0 = bias[c0], bb1 = bias[c0 + 1];
        const float v0 = leaky(fmaf((float)acc[n8][0], sa0 * sw0, bb0));
        const float v1 = leaky(fmaf((float)acc[n8][1], sa0 * sw1, bb1));
        const float v2 = leaky(fmaf((float)acc[n8][2], sa1 * sw0, bb0));
        const float v3 = leaky(fmaf((float)acc[n8][3], sa1 * sw1, bb1));
        if (FUSE) {
            const float w50 = w5[c0], w51 = w5[c0 + 1];
            zacc[0] += v0 * w50 + v1 * w51;
            zacc[1] += v2 * w50 + v3 * w51;
        } else {
            lm0 = fmaxf(lm0, fmaxf(fabsf(v0), fabsf(v1)));
            lm1 = fmaxf(lm1, fmaxf(fabsf(v2), fabsf(v3)));
            acc[n8][0] = __float_as_int(v0); acc[n8][1] = __float_as_int(v1);
            acc[n8][2] = __float_as_int(v2); acc[n8][3] = __float_as_int(v3);
        }
    }

    if (!FUSE) {
        atomicMax(&rmax[r0],     __float_as_uint(lm0));
        atomicMax(&rmax[r0 + 8], __float_as_uint(lm1));
        __syncthreads();
        if (tid < 64) {
            const float m = __uint_as_float(rmax[tid]);
            sqs[tid]   = (m > 0.f) ? 127.f / m : 0.f;
            dsOut[tid] = m * (1.f / 127.f);
            rmax[tid]  = 0u;
        }
        __syncthreads();
        const float q0s = sqs[r0], q1s = sqs[r0 + 8];
#pragma unroll
        for (int n8 = 0; n8 < N8; ++n8) {
            const int c0 = ncol0 + n8 * 8 + tq * 2;
            const int i0 = (int)rintf(__int_as_float(acc[n8][0]) * q0s);
            const int i1 = (int)rintf(__int_as_float(acc[n8][1]) * q0s);
            const int i2 = (int)rintf(__int_as_float(acc[n8][2]) * q1s);
            const int i3 = (int)rintf(__int_as_float(acc[n8][3]) * q1s);
            *(uint16_t*)(sD + r0 * DS + c0) =
                (uint16_t)((i0 & 0xFF) | ((i1 & 0xFF) << 8));
            *(uint16_t*)(sD + (r0 + 8) * DS + c0) =
                (uint16_t)((i2 & 0xFF) | ((i3 & 0xFF) << 8));
        }
    }
}

__global__ void __launch_bounds__(512, 2)
disc_kernel(const float* __restrict__ x, const float* __restrict__ lbl,
            const float* __restrict__ b1, const float* __restrict__ b2,
            const float* __restrict__ b3, const float* __restrict__ b4,
            const float* __restrict__ W5, const float* __restrict__ b5)
{
    extern __shared__ char sm[];
    int8_t* xs = (int8_t*)(sm + SO_XS);
    int8_t* h1 = (int8_t*)(sm + SO_H1);
    int8_t* h2 = (int8_t*)(sm + SO_H2);
    int8_t* h3 = (int8_t*)(sm + SO_H3);
    char*  ring = sm + SO_RING;
    float* sbias = (float*)(sm + SO_BIAS);
    float* sw5   = (float*)(sm + SO_W5);
    float* ssw   = (float*)(sm + SO_SW);
    float* ds0   = (float*)(sm + SO_DS0);
    float* ds1   = (float*)(sm + SO_DS1);
    float* sqs   = (float*)(sm + SO_QS);
    unsigned* rmax = (unsigned*)(sm + SO_RMAX);
    float* zs  = (float*)(sm + SO_ZS);
    float* red = (float*)(sm + SO_RED);

    const int tid = threadIdx.x, wid = tid >> 5, lane = tid & 31;
    const int wm = wid >> 2, wn = wid & 3;
    const int P0 = blockIdx.x * 64;
    const int b  = P0 / HW_, s0 = P0 % HW_;

    stage_chunk(0, ring, tid);
    stage_chunk(1, ring, tid);
    stage_chunk(2, ring, tid);

    for (int i = tid; i < 960; i += 512) {
        sbias[i] = (i < 64) ? b1[i] : (i < 192) ? b2[i - 64]
                 : (i < 448) ? b3[i - 192] : b4[i - 448];
        ssw[i] = g_sw[i];
    }
    if (tid < 512) sw5[tid] = W5[tid];
    if (tid < 64) { rmax[tid] = 0u; zs[tid] = 0.f; }

    // x tile: 8 threads per pixel (3 channels each), per-pixel dynamic scale
    {
        const int p = tid >> 3, q8 = tid & 7;
        float xv[3]; float m = 0.f;
#pragma unroll
        for (int j = 0; j < 3; ++j) {
            const int c = q8 * 3 + j;
            xv[j] = (c < 19) ? x[(b * 19 + c) * HW_ + s0 + p] : 0.f;
            m = fmaxf(m, fabsf(xv[j]));
        }
        m = fmaxf(m, __shfl_xor_sync(0xffffffffu, m, 1));
        m = fmaxf(m, __shfl_xor_sync(0xffffffffu, m, 2));
        m = fmaxf(m, __shfl_xor_sync(0xffffffffu, m, 4));
        const float qsx = (m > 0.f) ? 127.f / m : 0.f;
        if (q8 == 0) ds0[p] = m * (1.f / 127.f);
#pragma unroll
        for (int j = 0; j < 3; ++j) {
            const int c = q8 * 3 + j;
            if (c < 19) xs[p * 48 + c] = (int8_t)(int)rintf(xv[j] * qsx);
        }
        for (int i = tid; i < 64 * 13; i += 512) {    // zero-pad k 19..31
            const int pp = i / 13, cc = 19 + i % 13;
            xs[pp * 48 + cc] = 0;
        }
    }

    int chunk = 0;
    run_pass<32,  16, 48,  80,  false>(xs, h1, ring, sbias,       ssw,       ds0, ds1, sqs, rmax,
                                       nullptr, nullptr, wn * 16, 0, chunk, wm, lane, tid);
    run_pass<64,  32, 80,  144, false>(h1, h2, ring, sbias + 64,  ssw + 64,  ds1, ds0, sqs, rmax,
                                       nullptr, nullptr, wn * 32, 0, chunk, wm, lane, tid);
    run_pass<128, 64, 144, 272, false>(h2, h3, ring, sbias + 192, ssw + 192, ds0, ds1, sqs, rmax,
                                       nullptr, nullptr, wn * 64, 0, chunk, wm, lane, tid);

    float zacc[2] = {0.f, 0.f};
    run_pass<256, 64, 272, 1, true>(h3, nullptr, ring, sbias + 448, ssw + 448, ds1,
                                    nullptr, nullptr, nullptr, sw5, zacc,
                                    wn * 64, 0, chunk, wm, lane, tid);
    run_pass<256, 64, 272, 1, true>(h3, nullptr, ring, sbias + 448, ssw + 448, ds1,
                                    nullptr, nullptr, nullptr, sw5, zacc,
                                    256 + wn * 64, 256, chunk, wm, lane, tid);

    zacc[0] += __shfl_xor_sync(0xffffffffu, zacc[0], 1);
    zacc[0] += __shfl_xor_sync(0xffffffffu, zacc[0], 2);
    zacc[1] += __shfl_xor_sync(0xffffffffu, zacc[1], 1);
    zacc[1] += __shfl_xor_sync(0xffffffffu, zacc[1], 2);
    if ((lane & 3) == 0) {
        const int r0 = wm * 16 + (lane >> 2);
        atomicAdd(&zs[r0],     zacc[0]);
        atomicAdd(&zs[r0 + 8], zacc[1]);
    }
    __syncthreads();

    if (tid < 64) {
        const float z = zs[tid] + b5[0];
        const float l = lbl[P0 + tid];
        float bce = fmaxf(z, 0.f) - z * l + log1pf(expf(-fabsf(z)));
#pragma unroll
        for (int o = 16; o > 0; o >>= 1) bce += __shfl_xor_sync(0xffffffffu, bce, o);
        if (lane == 0) red[wid] = bce;
    }
    __syncthreads();
    if (tid == 0) atomicAdd(&g_acc, (double)(red[0] + red[1]));
}

__global__ void fin_kernel(float* out) {
    out[0] = (float)(g_acc * (1.0 / (double)NPIX));
}

extern "C" void kernel_launch(void* const* d_in, const int* in_sizes, int n_in,
                              void* d_out, int out_size) {
    (void)in_sizes; (void)n_in; (void)out_size;
    const float* x   = (const float*)d_in[0];
    const float* lbl = (const float*)d_in[1];
    const float* W1  = (const float*)d_in[2];
    const float* b1  = (const float*)d_in[3];
    const float* W2  = (const float*)d_in[4];
    const float* b2  = (const float*)d_in[5];
    const float* W3  = (const float*)d_in[6];
    const float* b3  = (const float*)d_in[7];
    const float* W4  = (const float*)d_in[8];
    const float* b4  = (const float*)d_in[9];
    const float* W5  = (const float*)d_in[10];
    const float* b5  = (const float*)d_in[11];

    cudaFuncSetAttribute(disc_kernel, cudaFuncAttributeMaxDynamicSharedMemorySize, SMEM_BYTES);

    prep_kernel<<<120, 256>>>(W1, W2, W3, W4);
    disc_kernel<<<NPIX / 64, 512, SMEM_BYTES>>>(x, lbl, b1, b2, b3, b4, W5, b5);
    fin_kernel<<<1, 1>>>((float*)d_out);
}